// round 15
// baseline (speedup 1.0000x reference)
#include <cuda_runtime.h>
#include <cuda_fp16.h>

#define FULLMASK 0xffffffffu
#define DIN   128
#define HC    256
#define NHEAD 4
#define CH    64
#define NMAX  50016
#define EMAX  900000
#define CHUNK0 25088   // multiple of 128

// ---------------- scratch (device globals; no allocation allowed) -----------
__device__ __half g_h[(size_t)NMAX * HC];     // layer-1 GEMM output (fp16)
__device__ __half g_h2[(size_t)NMAX * HC];    // layer-2 GEMM output (fp16)
__device__ __half g_xh[(size_t)NMAX * DIN];   // x split hi
__device__ __half g_xl[(size_t)NMAX * DIN];   // x split lo
__device__ __half g_acth[(size_t)NMAX * HC];  // act split hi
__device__ __half g_actl[(size_t)NMAX * HC];  // act split lo
__device__ __half g_w1h[DIN * HC];            // W1 rounded to fp16
__device__ __half g_w2h[HC * HC];             // W2 rounded to fp16
__device__ float  g_asrc[NMAX * NHEAD];       // layer-1 attention coeffs
__device__ float  g_adst[NMAX * NHEAD];
__device__ float  g_asrc2[NMAX * NHEAD];      // layer-2 attention coeffs
__device__ float  g_adst2[NMAX * NHEAD];
__device__ int    g_rowptr[NMAX + 1];
__device__ int    g_deg[NMAX];
__device__ int    g_cursor[NMAX];
__device__ int    g_csrc[EMAX];

// ---------------- helpers ---------------------------------------------------
static __device__ __forceinline__ float leaky(float x) { return fmaxf(x, 0.2f * x); }
static __device__ __forceinline__ float sel4(float4 v, int h) {
    return h == 0 ? v.x : (h == 1 ? v.y : (h == 2 ? v.z : v.w));
}
static __device__ __forceinline__ unsigned packh2(float e0, float e1) {
    unsigned r;
    asm("cvt.rn.f16x2.f32 %0, %1, %2;" : "=r"(r) : "f"(e1), "f"(e0));
    return r;
}
static __device__ __forceinline__ float2 unpackh2(unsigned h) {
    __half2 hh = *reinterpret_cast<__half2*>(&h);
    return __half22float2(hh);
}

static __device__ __forceinline__ void mma16f(float* d, const unsigned* a,
                                              unsigned b0, unsigned b1) {
    asm volatile(
        "mma.sync.aligned.m16n8k16.row.col.f32.f16.f16.f32 "
        "{%0,%1,%2,%3},{%4,%5,%6,%7},{%8,%9},{%0,%1,%2,%3};"
        : "+f"(d[0]), "+f"(d[1]), "+f"(d[2]), "+f"(d[3])
        : "r"(a[0]), "r"(a[1]), "r"(a[2]), "r"(a[3]), "r"(b0), "r"(b1));
}
static __device__ __forceinline__ void ldsm_x4(unsigned& r0, unsigned& r1,
                                               unsigned& r2, unsigned& r3, unsigned a) {
    asm volatile("ldmatrix.sync.aligned.m8n8.x4.shared.b16 {%0,%1,%2,%3}, [%4];"
                 : "=r"(r0), "=r"(r1), "=r"(r2), "=r"(r3) : "r"(a));
}
static __device__ __forceinline__ void ldsm_x2t(unsigned& r0, unsigned& r1, unsigned a) {
    asm volatile("ldmatrix.sync.aligned.m8n8.x2.trans.shared.b16 {%0,%1}, [%2];"
                 : "=r"(r0), "=r"(r1) : "r"(a));
}

// ---------------- operand preparation ----------------------------------------
__global__ void split_x_kernel(const float* __restrict__ x,
                               __half* __restrict__ xh, __half* __restrict__ xl,
                               int nquads) {
    int i = blockIdx.x * blockDim.x + threadIdx.x;
    if (i >= nquads) return;
    float4 v = ((const float4*)x)[i];
    unsigned h01 = packh2(v.x, v.y), h23 = packh2(v.z, v.w);
    float2 f01 = unpackh2(h01), f23 = unpackh2(h23);
    unsigned l01 = packh2(v.x - f01.x, v.y - f01.y);
    unsigned l23 = packh2(v.z - f23.x, v.w - f23.y);
    ((uint2*)xh)[i] = make_uint2(h01, h23);
    ((uint2*)xl)[i] = make_uint2(l01, l23);
}

__global__ void round_w_kernel(const float* __restrict__ w, __half* __restrict__ wh,
                               int nquads) {
    int i = blockIdx.x * blockDim.x + threadIdx.x;
    if (i >= nquads) return;
    float4 v = ((const float4*)w)[i];
    ((uint2*)wh)[i] = make_uint2(packh2(v.x, v.y), packh2(v.z, v.w));
}

// ---------------- CSR build --------------------------------------------------
__global__ void zero2_kernel(int* a, int* b, int n) {
    int i = blockIdx.x * blockDim.x + threadIdx.x;
    if (i < n) { a[i] = 0; b[i] = 0; }
}

__global__ void hist_kernel(const int* __restrict__ ei, int E, int* __restrict__ deg) {
    int i = blockIdx.x * blockDim.x + threadIdx.x;
    if (i < E) atomicAdd(&deg[ei[E + i]], 1);
}

__global__ void scan_kernel(const int* __restrict__ deg, int* __restrict__ rowptr, int n) {
    __shared__ int partials[1024];
    int tid = threadIdx.x;
    int per = (n + 1023) >> 10;
    int start = tid * per;
    int end = min(start + per, n);
    int s = 0;
    for (int i = start; i < end; i++) s += deg[i];
    partials[tid] = s;
    __syncthreads();
    for (int d = 1; d < 1024; d <<= 1) {
        int v = (tid >= d) ? partials[tid - d] : 0;
        __syncthreads();
        partials[tid] += v;
        __syncthreads();
    }
    int run = partials[tid] - s;  // exclusive prefix
    for (int i = start; i < end; i++) { rowptr[i] = run; run += deg[i]; }
    if (end == n) rowptr[n] = run;
}

__global__ void scatter_kernel(const int* __restrict__ ei, int E,
                               const int* __restrict__ rowptr,
                               int* __restrict__ cursor, int* __restrict__ csrc) {
    int i = blockIdx.x * blockDim.x + threadIdx.x;
    if (i < E) {
        int d = ei[E + i];
        int pos = atomicAdd(&cursor[d], 1);
        csrc[rowptr[d] + pos] = ei[i];
    }
}

// ---------------- fp16 2-term GEMM (pre-split A, pre-rounded B) --------------
#define A_ST_H 40
#define B_ST_H 136
#define A_TILE_H (128 * A_ST_H)
#define B_TILE_H (32 * B_ST_H)
#define STAGE_BYTES ((2 * A_TILE_H + B_TILE_H) * 2)
#define GEMM_SMEM (2 * STAGE_BYTES)

__global__ __launch_bounds__(256) void gemm_f16_kernel(
    const __half* __restrict__ AhG, const __half* __restrict__ AlG,
    const __half* __restrict__ BhG,
    __half* __restrict__ C,
    const float* __restrict__ attS, const float* __restrict__ attD,
    float* __restrict__ asrc, float* __restrict__ adst,
    int M, int K, int Nn) {
    extern __shared__ char smc[];
    const unsigned ubase = (unsigned)__cvta_generic_to_shared(smc);

    const int t = threadIdx.x;
    const int lane = t & 31;
    const int warpid = t >> 5;
    const int wm = warpid & 3;
    const int wn = warpid >> 2;
    const int m0 = blockIdx.x * 128;
    const int n0 = blockIdx.y * 128;
    const int g = lane >> 2, q = lane & 3;

    float acc[2][8][4];
#pragma unroll
    for (int mi = 0; mi < 2; mi++)
#pragma unroll
        for (int ni = 0; ni < 8; ni++)
#pragma unroll
            for (int w = 0; w < 4; w++) acc[mi][ni][w] = 0.f;

    const int ntiles = K >> 5;

    auto issue = [&](int tile, int stage) {
        const int kt = tile << 5;
        unsigned ahB = ubase + stage * STAGE_BYTES;
        unsigned alB = ahB + A_TILE_H * 2;
        unsigned bB  = alB + A_TILE_H * 2;
#pragma unroll
        for (int i = 0; i < 2; i++) {
            int c = i * 256 + t;
            int row = c >> 2, kq = c & 3;
            bool valid = (m0 + row) < M;
            size_t off = (size_t)(valid ? (m0 + row) : 0) * K + kt + kq * 8;
            unsigned d1 = ahB + row * 80 + kq * 16;
            unsigned d2 = alB + row * 80 + kq * 16;
            int sz = valid ? 16 : 0;
            asm volatile("cp.async.ca.shared.global [%0], [%1], 16, %2;"
                         :: "r"(d1), "l"(AhG + off), "r"(sz));
            asm volatile("cp.async.ca.shared.global [%0], [%1], 16, %2;"
                         :: "r"(d2), "l"(AlG + off), "r"(sz));
        }
#pragma unroll
        for (int i = 0; i < 2; i++) {
            int c = i * 256 + t;
            int r = c >> 4, c16 = c & 15;
            const __half* src = BhG + (size_t)(kt + r) * Nn + n0 + c16 * 8;
            unsigned dst = bB + r * 272 + c16 * 16;
            asm volatile("cp.async.ca.shared.global [%0], [%1], 16;"
                         :: "r"(dst), "l"(src));
        }
        asm volatile("cp.async.commit_group;");
    };

    issue(0, 0);

    for (int tile = 0; tile < ntiles; tile++) {
        const int cur = tile & 1;
        if (tile + 1 < ntiles) {
            issue(tile + 1, cur ^ 1);
            asm volatile("cp.async.wait_group 1;");
        } else {
            asm volatile("cp.async.wait_group 0;");
        }
        __syncthreads();
        unsigned ahB = ubase + cur * STAGE_BYTES;
        unsigned alB = ahB + A_TILE_H * 2;
        unsigned bB  = alB + A_TILE_H * 2;

#pragma unroll
        for (int k16 = 0; k16 < 2; k16++) {
            const int kk = k16 * 16;
            unsigned ah[2][4], al[2][4];
#pragma unroll
            for (int mi = 0; mi < 2; mi++) {
                unsigned rowoff = (unsigned)((wm * 32 + mi * 16 + (lane & 15)) * 80 +
                                             (kk + ((lane >> 4) << 3)) * 2);
                ldsm_x4(ah[mi][0], ah[mi][1], ah[mi][2], ah[mi][3], ahB + rowoff);
                ldsm_x4(al[mi][0], al[mi][1], al[mi][2], al[mi][3], alB + rowoff);
            }
#pragma unroll
            for (int ni = 0; ni < 8; ni++) {
                unsigned baddr = bB + (unsigned)((kk + (lane & 15)) * 272 +
                                                 (wn * 64 + ni * 8) * 2);
                unsigned b0, b1;
                ldsm_x2t(b0, b1, baddr);
                mma16f(acc[0][ni], ah[0], b0, b1);
                mma16f(acc[0][ni], al[0], b0, b1);
                mma16f(acc[1][ni], ah[1], b0, b1);
                mma16f(acc[1][ni], al[1], b0, b1);
            }
        }
        __syncthreads();
    }

    const int head = blockIdx.y * 2 + wn;
    float2 sS[8], sD[8];
#pragma unroll
    for (int ni = 0; ni < 8; ni++) {
        sS[ni] = *(const float2*)(attS + n0 + wn * 64 + ni * 8 + q * 2);
        sD[ni] = *(const float2*)(attD + n0 + wn * 64 + ni * 8 + q * 2);
    }

#pragma unroll
    for (int mi = 0; mi < 2; mi++) {
        int r0 = m0 + wm * 32 + mi * 16 + g;
        float ps0 = 0.f, pd0 = 0.f, ps1 = 0.f, pd1 = 0.f;
#pragma unroll
        for (int ni = 0; ni < 8; ni++) {
            int cc = n0 + wn * 64 + ni * 8 + q * 2;
            if (r0 < M)
                *(__half2*)(C + (size_t)r0 * Nn + cc) =
                    __floats2half2_rn(acc[mi][ni][0], acc[mi][ni][1]);
            if (r0 + 8 < M)
                *(__half2*)(C + (size_t)(r0 + 8) * Nn + cc) =
                    __floats2half2_rn(acc[mi][ni][2], acc[mi][ni][3]);
            ps0 += acc[mi][ni][0] * sS[ni].x + acc[mi][ni][1] * sS[ni].y;
            pd0 += acc[mi][ni][0] * sD[ni].x + acc[mi][ni][1] * sD[ni].y;
            ps1 += acc[mi][ni][2] * sS[ni].x + acc[mi][ni][3] * sS[ni].y;
            pd1 += acc[mi][ni][2] * sD[ni].x + acc[mi][ni][3] * sD[ni].y;
        }
#pragma unroll
        for (int o = 1; o < 4; o <<= 1) {
            ps0 += __shfl_xor_sync(FULLMASK, ps0, o);
            pd0 += __shfl_xor_sync(FULLMASK, pd0, o);
            ps1 += __shfl_xor_sync(FULLMASK, ps1, o);
            pd1 += __shfl_xor_sync(FULLMASK, pd1, o);
        }
        if (q == 0) {
            if (r0 < M) {
                asrc[r0 * 4 + head] = ps0;
                adst[r0 * 4 + head] = pd0;
            }
            if (r0 + 8 < M) {
                asrc[(r0 + 8) * 4 + head] = ps1;
                adst[(r0 + 8) * 4 + head] = pd1;
            }
        }
    }
}

// ---------------- per-node aggregation core (R8-proven) -----------------------
static __device__ __forceinline__ void agg_core(const __half* __restrict__ hbuf,
                                                const float* __restrict__ asrc,
                                                const float* __restrict__ adst,
                                                const int* __restrict__ rowptr,
                                                const int* __restrict__ csrc,
                                                int gw, int lane,
                                                float4& acc0, float4& acc1) {
    int hsel = lane >> 3;
    int beg = rowptr[gw], end = rowptr[gw + 1];
    float4 ad = *(const float4*)(adst + gw * 4);

    // phase 1: segment max (per head)
    float4 mx = make_float4(-1e30f, -1e30f, -1e30f, -1e30f);
    for (int j = beg + lane; j < end; j += 32) {
        int s = csrc[j];
        float4 as = *(const float4*)(asrc + s * 4);
        mx.x = fmaxf(mx.x, leaky(as.x + ad.x));
        mx.y = fmaxf(mx.y, leaky(as.y + ad.y));
        mx.z = fmaxf(mx.z, leaky(as.z + ad.z));
        mx.w = fmaxf(mx.w, leaky(as.w + ad.w));
    }
#pragma unroll
    for (int o = 16; o; o >>= 1) {
        mx.x = fmaxf(mx.x, __shfl_xor_sync(FULLMASK, mx.x, o));
        mx.y = fmaxf(mx.y, __shfl_xor_sync(FULLMASK, mx.y, o));
        mx.z = fmaxf(mx.z, __shfl_xor_sync(FULLMASK, mx.z, o));
        mx.w = fmaxf(mx.w, __shfl_xor_sync(FULLMASK, mx.w, o));
    }

    // phase 2: exp-sum
    float4 sm = make_float4(0.f, 0.f, 0.f, 0.f);
    for (int j = beg + lane; j < end; j += 32) {
        int s = csrc[j];
        float4 as = *(const float4*)(asrc + s * 4);
        sm.x += __expf(leaky(as.x + ad.x) - mx.x);
        sm.y += __expf(leaky(as.y + ad.y) - mx.y);
        sm.z += __expf(leaky(as.z + ad.z) - mx.z);
        sm.w += __expf(leaky(as.w + ad.w) - mx.w);
    }
#pragma unroll
    for (int o = 16; o; o >>= 1) {
        sm.x += __shfl_xor_sync(FULLMASK, sm.x, o);
        sm.y += __shfl_xor_sync(FULLMASK, sm.y, o);
        sm.z += __shfl_xor_sync(FULLMASK, sm.z, o);
        sm.w += __shfl_xor_sync(FULLMASK, sm.w, o);
    }
    float4 inv = make_float4(1.f / (sm.x + 1e-16f), 1.f / (sm.y + 1e-16f),
                             1.f / (sm.z + 1e-16f), 1.f / (sm.w + 1e-16f));
    float mh = sel4(mx, hsel), ih = sel4(inv, hsel), adh = sel4(ad, hsel);

    // phase 3: weighted gather-accumulate, 2 edges per iteration
    acc0 = make_float4(0.f, 0.f, 0.f, 0.f);
    acc1 = make_float4(0.f, 0.f, 0.f, 0.f);
    const int cbase = lane * 8;
    int j = beg;
    for (; j + 2 <= end; j += 2) {
        int s0 = csrc[j], s1 = csrc[j + 1];
        float as0 = asrc[s0 * 4 + hsel];
        float as1 = asrc[s1 * 4 + hsel];
        union { uint4 u; __half2 h2[4]; } u0, u1;
        u0.u = *(const uint4*)(hbuf + (size_t)s0 * HC + cbase);
        u1.u = *(const uint4*)(hbuf + (size_t)s1 * HC + cbase);
        float a0 = __expf(leaky(as0 + adh) - mh) * ih;
        float a1 = __expf(leaky(as1 + adh) - mh) * ih;
        float2 p;
        p = __half22float2(u0.h2[0]); acc0.x = fmaf(p.x, a0, acc0.x); acc0.y = fmaf(p.y, a0, acc0.y);
        p = __half22float2(u0.h2[1]); acc0.z = fmaf(p.x, a0, acc0.z); acc0.w = fmaf(p.y, a0, acc0.w);
        p = __half22float2(u0.h2[2]); acc1.x = fmaf(p.x, a0, acc1.x); acc1.y = fmaf(p.y, a0, acc1.y);
        p = __half22float2(u0.h2[3]); acc1.z = fmaf(p.x, a0, acc1.z); acc1.w = fmaf(p.y, a0, acc1.w);
        p = __half22float2(u1.h2[0]); acc0.x = fmaf(p.x, a1, acc0.x); acc0.y = fmaf(p.y, a1, acc0.y);
        p = __half22float2(u1.h2[1]); acc0.z = fmaf(p.x, a1, acc0.z); acc0.w = fmaf(p.y, a1, acc0.w);
        p = __half22float2(u1.h2[2]); acc1.x = fmaf(p.x, a1, acc1.x); acc1.y = fmaf(p.y, a1, acc1.y);
        p = __half22float2(u1.h2[3]); acc1.z = fmaf(p.x, a1, acc1.z); acc1.w = fmaf(p.y, a1, acc1.w);
    }
    if (j < end) {
        int s = csrc[j];
        float as = asrc[s * 4 + hsel];
        float alpha = __expf(leaky(as + adh) - mh) * ih;
        union { uint4 u; __half2 h2[4]; } uu;
        uu.u = *(const uint4*)(hbuf + (size_t)s * HC + cbase);
        float2 p;
        p = __half22float2(uu.h2[0]); acc0.x = fmaf(p.x, alpha, acc0.x); acc0.y = fmaf(p.y, alpha, acc0.y);
        p = __half22float2(uu.h2[1]); acc0.z = fmaf(p.x, alpha, acc0.z); acc0.w = fmaf(p.y, alpha, acc0.w);
        p = __half22float2(uu.h2[2]); acc1.x = fmaf(p.x, alpha, acc1.x); acc1.y = fmaf(p.y, alpha, acc1.y);
        p = __half22float2(uu.h2[3]); acc1.z = fmaf(p.x, alpha, acc1.z); acc1.w = fmaf(p.y, alpha, acc1.w);
    }
}

// layer 1: concat epilogue (bias + relu), emits pre-split fp16 act (hi+lo).
// Chunked over destination nodes [base, limit).
__global__ __launch_bounds__(256) void agg1_kernel(const __half* __restrict__ hbuf,
                                                   const float* __restrict__ asrc,
                                                   const float* __restrict__ adst,
                                                   const int* __restrict__ rowptr,
                                                   const int* __restrict__ csrc,
                                                   const float* __restrict__ bias,
                                                   __half* __restrict__ acth,
                                                   __half* __restrict__ actl,
                                                   int base, int limit) {
    int gw = base + ((blockIdx.x * blockDim.x + threadIdx.x) >> 5);
    int lane = threadIdx.x & 31;
    if (gw >= limit) return;
    float4 acc0, acc1;
    agg_core(hbuf, asrc, adst, rowptr, csrc, gw, lane, acc0, acc1);
    int cbase = lane * 8;
    float4 b0 = *(const float4*)(bias + cbase);
    float4 b1 = *(const float4*)(bias + cbase + 4);
    float v[8] = {fmaxf(acc0.x + b0.x, 0.f), fmaxf(acc0.y + b0.y, 0.f),
                  fmaxf(acc0.z + b0.z, 0.f), fmaxf(acc0.w + b0.w, 0.f),
                  fmaxf(acc1.x + b1.x, 0.f), fmaxf(acc1.y + b1.y, 0.f),
                  fmaxf(acc1.z + b1.z, 0.f), fmaxf(acc1.w + b1.w, 0.f)};
    unsigned hh[4], ll[4];
#pragma unroll
    for (int p = 0; p < 4; p++) {
        hh[p] = packh2(v[2 * p], v[2 * p + 1]);
        float2 f = unpackh2(hh[p]);
        ll[p] = packh2(v[2 * p] - f.x, v[2 * p + 1] - f.y);
    }
    *(uint4*)(acth + (size_t)gw * HC + cbase) = make_uint4(hh[0], hh[1], hh[2], hh[3]);
    *(uint4*)(actl + (size_t)gw * HC + cbase) = make_uint4(ll[0], ll[1], ll[2], ll[3]);
}

// layer 2: head-mean + bias + relu + softmax(64) -> [N,64]
__global__ __launch_bounds__(256) void agg2_kernel(const __half* __restrict__ hbuf,
                                                   const float* __restrict__ asrc,
                                                   const float* __restrict__ adst,
                                                   const int* __restrict__ rowptr,
                                                   const int* __restrict__ csrc,
                                                   const float* __restrict__ bias,
                                                   float* __restrict__ outp, int N) {
    int gw = (blockIdx.x * blockDim.x + threadIdx.x) >> 5;
    int lane = threadIdx.x & 31;
    if (gw >= N) return;
    float4 acc0, acc1;
    agg_core(hbuf, asrc, adst, rowptr, csrc, gw, lane, acc0, acc1);

    float r[8] = {acc0.x, acc0.y, acc0.z, acc0.w, acc1.x, acc1.y, acc1.z, acc1.w};
#pragma unroll
    for (int k = 0; k < 8; k++) {
        r[k] += __shfl_xor_sync(FULLMASK, r[k], 8);
        r[k] += __shfl_xor_sync(FULLMASK, r[k], 16);
    }
    int cp = (lane & 7) * 8;
    float4 b0 = *(const float4*)(bias + cp);
    float4 b1 = *(const float4*)(bias + cp + 4);
    float bb[8] = {b0.x, b0.y, b0.z, b0.w, b1.x, b1.y, b1.z, b1.w};
    float lm = -1e30f;
#pragma unroll
    for (int k = 0; k < 8; k++) {
        r[k] = fmaxf(0.25f * r[k] + bb[k], 0.f);
        lm = fmaxf(lm, r[k]);
    }
#pragma unroll
    for (int o = 4; o; o >>= 1) lm = fmaxf(lm, __shfl_xor_sync(FULLMASK, lm, o));
    float ls = 0.f;
#pragma unroll
    for (int k = 0; k < 8; k++) { r[k] = __expf(r[k] - lm); ls += r[k]; }
#pragma unroll
    for (int o = 4; o; o >>= 1) ls += __shfl_xor_sync(FULLMASK, ls, o);
    float invs = 1.f / ls;
    if (lane < 8) {
        float* op = outp + (size_t)gw * CH + lane * 8;
        ((float4*)op)[0] = make_float4(r[0] * invs, r[1] * invs, r[2] * invs, r[3] * invs);
        ((float4*)op)[1] = make_float4(r[4] * invs, r[5] * invs, r[6] * invs, r[7] * invs);
    }
}

// ---------------- launch -----------------------------------------------------
extern "C" void kernel_launch(void* const* d_in, const int* in_sizes, int n_in,
                              void* d_out, int out_size) {
    const float* x   = (const float*)d_in[0];
    const int*   ei  = (const int*)d_in[1];
    const float* W1  = (const float*)d_in[2];
    const float* as1 = (const float*)d_in[3];
    const float* ad1 = (const float*)d_in[4];
    const float* b1  = (const float*)d_in[5];
    const float* W2  = (const float*)d_in[6];
    const float* as2 = (const float*)d_in[7];
    const float* ad2 = (const float*)d_in[8];
    const float* b2  = (const float*)d_in[9];
    float* out = (float*)d_out;

    const int N = in_sizes[0] / DIN;
    const int E = in_sizes[1] / 2;

    __half *dH, *dH2, *dXh, *dXl, *dAh, *dAl, *dW1h, *dW2h;
    float *dAs, *dAd, *dAs2, *dAd2;
    int *dRow, *dDeg, *dCur, *dCsr;
    cudaGetSymbolAddress((void**)&dH, g_h);
    cudaGetSymbolAddress((void**)&dH2, g_h2);
    cudaGetSymbolAddress((void**)&dXh, g_xh);
    cudaGetSymbolAddress((void**)&dXl, g_xl);
    cudaGetSymbolAddress((void**)&dAh, g_acth);
    cudaGetSymbolAddress((void**)&dAl, g_actl);
    cudaGetSymbolAddress((void**)&dW1h, g_w1h);
    cudaGetSymbolAddress((void**)&dW2h, g_w2h);
    cudaGetSymbolAddress((void**)&dAs, g_asrc);
    cudaGetSymbolAddress((void**)&dAd, g_adst);
    cudaGetSymbolAddress((void**)&dAs2, g_asrc2);
    cudaGetSymbolAddress((void**)&dAd2, g_adst2);
    cudaGetSymbolAddress((void**)&dRow, g_rowptr);
    cudaGetSymbolAddress((void**)&dDeg, g_deg);
    cudaGetSymbolAddress((void**)&dCur, g_cursor);
    cudaGetSymbolAddress((void**)&dCsr, g_csrc);

    cudaFuncSetAttribute(gemm_f16_kernel,
                         cudaFuncAttributeMaxDynamicSharedMemorySize, GEMM_SMEM);

    static cudaStream_t s2 = [] { cudaStream_t s; cudaStreamCreate(&s); return s; }();
    static cudaStream_t s3 = [] { cudaStream_t s; cudaStreamCreate(&s); return s; }();
    static cudaEvent_t evFork = [] {
        cudaEvent_t e; cudaEventCreateWithFlags(&e, cudaEventDisableTiming); return e; }();
    static cudaEvent_t evJoin = [] {
        cudaEvent_t e; cudaEventCreateWithFlags(&e, cudaEventDisableTiming); return e; }();
    static cudaEvent_t evA0 = [] {
        cudaEvent_t e; cudaEventCreateWithFlags(&e, cudaEventDisableTiming); return e; }();
    static cudaEvent_t evG0 = [] {
        cudaEvent_t e; cudaEventCreateWithFlags(&e, cudaEventDisableTiming); return e; }();

    const int c0 = (CHUNK0 < N) ? CHUNK0 : N;  // chunk boundary (multiple of 128)
    const int c1 = N - c0;

    const int warpBlocksAll = (N * 32 + 255) / 256;
    const int warpBlocks0 = (c0 * 32 + 255) / 256;
    const int warpBlocks1 = (c1 * 32 + 255) / 256;
    dim3 gg((N + 127) / 128, HC / 128);
    dim3 gg0(c0 / 128, HC / 128);
    dim3 gg1((c1 + 127) / 128, HC / 128);

    // fork: CSR build (+ W2 rounding, needed only at GEMM2) on s2
    cudaEventRecord(evFork, 0);
    cudaStreamWaitEvent(s2, evFork, 0);

    zero2_kernel<<<(N + 255) / 256, 256, 0, s2>>>(dDeg, dCur, N);
    hist_kernel<<<(E + 255) / 256, 256, 0, s2>>>(ei, E, dDeg);
    scan_kernel<<<1, 1024, 0, s2>>>(dDeg, dRow, N);
    scatter_kernel<<<(E + 255) / 256, 256, 0, s2>>>(ei, E, dRow, dCur, dCsr);
    round_w_kernel<<<(HC * HC / 4 + 255) / 256, 256, 0, s2>>>(W2, dW2h, HC * HC / 4);
    cudaEventRecord(evJoin, s2);

    // operand prep on main
    int xq = N * DIN / 4;
    split_x_kernel<<<(xq + 255) / 256, 256>>>(x, dXh, dXl, xq);
    round_w_kernel<<<(DIN * HC / 4 + 255) / 256, 256>>>(W1, dW1h, DIN * HC / 4);

    // layer 1 GEMM (+ fused attention coefficients) -> dH, dAs, dAd
    gemm_f16_kernel<<<gg, 256, GEMM_SMEM>>>(dXh, dXl, dW1h, dH, as1, ad1,
                                            dAs, dAd, N, DIN, HC);

    // join: aggregation needs the CSR (W2h ready transitively via evJoin)
    cudaStreamWaitEvent(0, evJoin, 0);

    // agg1 chunk 0 -> acth/actl[0,c0); then GEMM2 chunk 0 on s3 writes the
    // SEPARATE layer-2 buffers (dH2/dAs2/dAd2) while agg1 chunk 1 reads the
    // untouched layer-1 buffers (dH/dAs/dAd) on main. No buffer is both read
    // and written concurrently.
    agg1_kernel<<<warpBlocks0, 256>>>(dH, dAs, dAd, dRow, dCsr, b1, dAh, dAl, 0, c0);
    cudaEventRecord(evA0, 0);
    cudaStreamWaitEvent(s3, evA0, 0);
    gemm_f16_kernel<<<gg0, 256, GEMM_SMEM, s3>>>(
        dAh, dAl, dW2h, dH2, as2, ad2, dAs2, dAd2, c0, HC, HC);
    cudaEventRecord(evG0, s3);

    if (c1 > 0) {
        agg1_kernel<<<warpBlocks1, 256>>>(dH, dAs, dAd, dRow, dCsr, b1, dAh, dAl, c0, N);
        gemm_f16_kernel<<<gg1, 256, GEMM_SMEM>>>(
            dAh + (size_t)c0 * HC, dAl + (size_t)c0 * HC, dW2h,
            dH2 + (size_t)c0 * HC, as2, ad2,
            dAs2 + (size_t)c0 * 4, dAd2 + (size_t)c0 * 4, c1, HC, HC);
    }
    cudaStreamWaitEvent(0, evG0, 0);

    agg2_kernel<<<warpBlocksAll, 256>>>(dH2, dAs2, dAd2, dRow, dCsr, b2, out, N);
}

// round 16
// speedup vs baseline: 1.2516x; 1.2516x over previous
#include <cuda_runtime.h>
#include <cuda_fp16.h>

#define FULLMASK 0xffffffffu
#define DIN   128
#define HC    256
#define NHEAD 4
#define CH    64
#define NMAX  50016
#define EMAX  900000

// ---------------- scratch (device globals; no allocation allowed) -----------
__device__ __half g_h[(size_t)NMAX * HC];     // GEMM output (fp16, gather-only)
__device__ __half g_xh[(size_t)NMAX * DIN];   // x rounded to fp16
__device__ __half g_acth[(size_t)NMAX * HC];  // act rounded to fp16
__device__ __half g_w1h[DIN * HC];            // W1 rounded to fp16
__device__ __half g_w2h[HC * HC];             // W2 rounded to fp16
__device__ float  g_asrc[NMAX * NHEAD];
__device__ float  g_adst[NMAX * NHEAD];
__device__ int    g_rowptr[NMAX + 1];
__device__ int    g_deg[NMAX];
__device__ int    g_cursor[NMAX];
__device__ int    g_csrc[EMAX];

// ---------------- helpers ---------------------------------------------------
static __device__ __forceinline__ float leaky(float x) { return fmaxf(x, 0.2f * x); }
static __device__ __forceinline__ float sel4(float4 v, int h) {
    return h == 0 ? v.x : (h == 1 ? v.y : (h == 2 ? v.z : v.w));
}
static __device__ __forceinline__ unsigned packh2(float e0, float e1) {
    unsigned r;
    asm("cvt.rn.f16x2.f32 %0, %1, %2;" : "=r"(r) : "f"(e1), "f"(e0));
    return r;
}

static __device__ __forceinline__ void mma16f(float* d, const unsigned* a,
                                              unsigned b0, unsigned b1) {
    asm volatile(
        "mma.sync.aligned.m16n8k16.row.col.f32.f16.f16.f32 "
        "{%0,%1,%2,%3},{%4,%5,%6,%7},{%8,%9},{%0,%1,%2,%3};"
        : "+f"(d[0]), "+f"(d[1]), "+f"(d[2]), "+f"(d[3])
        : "r"(a[0]), "r"(a[1]), "r"(a[2]), "r"(a[3]), "r"(b0), "r"(b1));
}
static __device__ __forceinline__ void ldsm_x4(unsigned& r0, unsigned& r1,
                                               unsigned& r2, unsigned& r3, unsigned a) {
    asm volatile("ldmatrix.sync.aligned.m8n8.x4.shared.b16 {%0,%1,%2,%3}, [%4];"
                 : "=r"(r0), "=r"(r1), "=r"(r2), "=r"(r3) : "r"(a));
}
static __device__ __forceinline__ void ldsm_x2t(unsigned& r0, unsigned& r1, unsigned a) {
    asm volatile("ldmatrix.sync.aligned.m8n8.x2.trans.shared.b16 {%0,%1}, [%2];"
                 : "=r"(r0), "=r"(r1) : "r"(a));
}

// ---------------- operand preparation: round fp32 -> fp16 --------------------
__global__ void round_w_kernel(const float* __restrict__ w, __half* __restrict__ wh,
                               int nquads) {
    int i = blockIdx.x * blockDim.x + threadIdx.x;
    if (i >= nquads) return;
    float4 v = ((const float4*)w)[i];
    ((uint2*)wh)[i] = make_uint2(packh2(v.x, v.y), packh2(v.z, v.w));
}

// ---------------- CSR build --------------------------------------------------
__global__ void zero2_kernel(int* a, int* b, int n) {
    int i = blockIdx.x * blockDim.x + threadIdx.x;
    if (i < n) { a[i] = 0; b[i] = 0; }
}

__global__ void hist_kernel(const int* __restrict__ ei, int E, int* __restrict__ deg) {
    int i = blockIdx.x * blockDim.x + threadIdx.x;
    if (i < E) atomicAdd(&deg[ei[E + i]], 1);
}

__global__ void scan_kernel(const int* __restrict__ deg, int* __restrict__ rowptr, int n) {
    __shared__ int partials[1024];
    int tid = threadIdx.x;
    int per = (n + 1023) >> 10;
    int start = tid * per;
    int end = min(start + per, n);
    int s = 0;
    for (int i = start; i < end; i++) s += deg[i];
    partials[tid] = s;
    __syncthreads();
    for (int d = 1; d < 1024; d <<= 1) {
        int v = (tid >= d) ? partials[tid - d] : 0;
        __syncthreads();
        partials[tid] += v;
        __syncthreads();
    }
    int run = partials[tid] - s;  // exclusive prefix
    for (int i = start; i < end; i++) { rowptr[i] = run; run += deg[i]; }
    if (end == n) rowptr[n] = run;
}

__global__ void scatter_kernel(const int* __restrict__ ei, int E,
                               const int* __restrict__ rowptr,
                               int* __restrict__ cursor, int* __restrict__ csrc) {
    int i = blockIdx.x * blockDim.x + threadIdx.x;
    if (i < E) {
        int d = ei[E + i];
        int pos = atomicAdd(&cursor[d], 1);
        csrc[rowptr[d] + pos] = ei[i];
    }
}

// ---------------- fp16 1-term GEMM + fused attention epilogue ----------------
// C[M,Nn] (fp16) = rn16(A)[M,K] @ rn16(B)[K,Nn]; BM=128, BN=128, BK=32.
#define A_ST_H 40
#define B_ST_H 136
#define A_TILE_H (128 * A_ST_H)   // 5120 halves
#define B_TILE_H (32 * B_ST_H)    // 4352 halves
#define STAGE_BYTES ((A_TILE_H + B_TILE_H) * 2)   // 18944
#define GEMM_SMEM (2 * STAGE_BYTES)               // 37888

__global__ __launch_bounds__(256) void gemm_f16_kernel(
    const __half* __restrict__ AhG,
    const __half* __restrict__ BhG,
    __half* __restrict__ C,
    const float* __restrict__ attS, const float* __restrict__ attD,
    float* __restrict__ asrc, float* __restrict__ adst,
    int M, int K, int Nn) {
    extern __shared__ char smc[];
    const unsigned ubase = (unsigned)__cvta_generic_to_shared(smc);

    const int t = threadIdx.x;
    const int lane = t & 31;
    const int warpid = t >> 5;
    const int wm = warpid & 3;
    const int wn = warpid >> 2;
    const int m0 = blockIdx.x * 128;
    const int n0 = blockIdx.y * 128;
    const int g = lane >> 2, q = lane & 3;

    float acc[2][8][4];
#pragma unroll
    for (int mi = 0; mi < 2; mi++)
#pragma unroll
        for (int ni = 0; ni < 8; ni++)
#pragma unroll
            for (int w = 0; w < 4; w++) acc[mi][ni][w] = 0.f;

    const int ntiles = K >> 5;

    auto issue = [&](int tile, int stage) {
        const int kt = tile << 5;
        unsigned ahB = ubase + stage * STAGE_BYTES;
        unsigned bB  = ahB + A_TILE_H * 2;
#pragma unroll
        for (int i = 0; i < 2; i++) {
            int c = i * 256 + t;            // 0..511
            int row = c >> 2, kq = c & 3;   // 4x16B chunks per A row (64B)
            bool valid = (m0 + row) < M;
            size_t off = (size_t)(valid ? (m0 + row) : 0) * K + kt + kq * 8;
            unsigned d1 = ahB + row * 80 + kq * 16;
            int sz = valid ? 16 : 0;
            asm volatile("cp.async.ca.shared.global [%0], [%1], 16, %2;"
                         :: "r"(d1), "l"(AhG + off), "r"(sz));
        }
#pragma unroll
        for (int i = 0; i < 2; i++) {
            int c = i * 256 + t;            // 0..511
            int r = c >> 4, c16 = c & 15;   // 16x16B chunks per B row (256B)
            const __half* src = BhG + (size_t)(kt + r) * Nn + n0 + c16 * 8;
            unsigned dst = bB + r * 272 + c16 * 16;
            asm volatile("cp.async.ca.shared.global [%0], [%1], 16;"
                         :: "r"(dst), "l"(src));
        }
        asm volatile("cp.async.commit_group;");
    };

    issue(0, 0);

    for (int tile = 0; tile < ntiles; tile++) {
        const int cur = tile & 1;
        if (tile + 1 < ntiles) {
            issue(tile + 1, cur ^ 1);
            asm volatile("cp.async.wait_group 1;");
        } else {
            asm volatile("cp.async.wait_group 0;");
        }
        __syncthreads();
        unsigned ahB = ubase + cur * STAGE_BYTES;
        unsigned bB  = ahB + A_TILE_H * 2;

#pragma unroll
        for (int k16 = 0; k16 < 2; k16++) {
            const int kk = k16 * 16;
            unsigned ah[2][4];
#pragma unroll
            for (int mi = 0; mi < 2; mi++) {
                unsigned rowoff = (unsigned)((wm * 32 + mi * 16 + (lane & 15)) * 80 +
                                             (kk + ((lane >> 4) << 3)) * 2);
                ldsm_x4(ah[mi][0], ah[mi][1], ah[mi][2], ah[mi][3], ahB + rowoff);
            }
#pragma unroll
            for (int ni = 0; ni < 8; ni++) {
                unsigned baddr = bB + (unsigned)((kk + (lane & 15)) * 272 +
                                                 (wn * 64 + ni * 8) * 2);
                unsigned b0, b1;
                ldsm_x2t(b0, b1, baddr);
                mma16f(acc[0][ni], ah[0], b0, b1);
                mma16f(acc[1][ni], ah[1], b0, b1);
            }
        }
        __syncthreads();
    }

    // epilogue: store C (fp16) + fused per-head attention dot products
    const int head = blockIdx.y * 2 + wn;
    float2 sS[8], sD[8];
#pragma unroll
    for (int ni = 0; ni < 8; ni++) {
        sS[ni] = *(const float2*)(attS + n0 + wn * 64 + ni * 8 + q * 2);
        sD[ni] = *(const float2*)(attD + n0 + wn * 64 + ni * 8 + q * 2);
    }

#pragma unroll
    for (int mi = 0; mi < 2; mi++) {
        int r0 = m0 + wm * 32 + mi * 16 + g;
        float ps0 = 0.f, pd0 = 0.f, ps1 = 0.f, pd1 = 0.f;
#pragma unroll
        for (int ni = 0; ni < 8; ni++) {
            int cc = n0 + wn * 64 + ni * 8 + q * 2;
            if (r0 < M)
                *(__half2*)(C + (size_t)r0 * Nn + cc) =
                    __floats2half2_rn(acc[mi][ni][0], acc[mi][ni][1]);
            if (r0 + 8 < M)
                *(__half2*)(C + (size_t)(r0 + 8) * Nn + cc) =
                    __floats2half2_rn(acc[mi][ni][2], acc[mi][ni][3]);
            ps0 += acc[mi][ni][0] * sS[ni].x + acc[mi][ni][1] * sS[ni].y;
            pd0 += acc[mi][ni][0] * sD[ni].x + acc[mi][ni][1] * sD[ni].y;
            ps1 += acc[mi][ni][2] * sS[ni].x + acc[mi][ni][3] * sS[ni].y;
            pd1 += acc[mi][ni][2] * sD[ni].x + acc[mi][ni][3] * sD[ni].y;
        }
#pragma unroll
        for (int o = 1; o < 4; o <<= 1) {
            ps0 += __shfl_xor_sync(FULLMASK, ps0, o);
            pd0 += __shfl_xor_sync(FULLMASK, pd0, o);
            ps1 += __shfl_xor_sync(FULLMASK, ps1, o);
            pd1 += __shfl_xor_sync(FULLMASK, pd1, o);
        }
        if (q == 0) {
            if (r0 < M) {
                asrc[r0 * 4 + head] = ps0;
                adst[r0 * 4 + head] = pd0;
            }
            if (r0 + 8 < M) {
                asrc[(r0 + 8) * 4 + head] = ps1;
                adst[(r0 + 8) * 4 + head] = pd1;
            }
        }
    }
}

// ---------------- per-node aggregation core (R8-proven) -----------------------
static __device__ __forceinline__ void agg_core(const __half* __restrict__ hbuf,
                                                const float* __restrict__ asrc,
                                                const float* __restrict__ adst,
                                                const int* __restrict__ rowptr,
                                                const int* __restrict__ csrc,
                                                int gw, int lane,
                                                float4& acc0, float4& acc1) {
    int hsel = lane >> 3;
    int beg = rowptr[gw], end = rowptr[gw + 1];
    float4 ad = *(const float4*)(adst + gw * 4);

    // phase 1: segment max (per head)
    float4 mx = make_float4(-1e30f, -1e30f, -1e30f, -1e30f);
    for (int j = beg + lane; j < end; j += 32) {
        int s = csrc[j];
        float4 as = *(const float4*)(asrc + s * 4);
        mx.x = fmaxf(mx.x, leaky(as.x + ad.x));
        mx.y = fmaxf(mx.y, leaky(as.y + ad.y));
        mx.z = fmaxf(mx.z, leaky(as.z + ad.z));
        mx.w = fmaxf(mx.w, leaky(as.w + ad.w));
    }
#pragma unroll
    for (int o = 16; o; o >>= 1) {
        mx.x = fmaxf(mx.x, __shfl_xor_sync(FULLMASK, mx.x, o));
        mx.y = fmaxf(mx.y, __shfl_xor_sync(FULLMASK, mx.y, o));
        mx.z = fmaxf(mx.z, __shfl_xor_sync(FULLMASK, mx.z, o));
        mx.w = fmaxf(mx.w, __shfl_xor_sync(FULLMASK, mx.w, o));
    }

    // phase 2: exp-sum
    float4 sm = make_float4(0.f, 0.f, 0.f, 0.f);
    for (int j = beg + lane; j < end; j += 32) {
        int s = csrc[j];
        float4 as = *(const float4*)(asrc + s * 4);
        sm.x += __expf(leaky(as.x + ad.x) - mx.x);
        sm.y += __expf(leaky(as.y + ad.y) - mx.y);
        sm.z += __expf(leaky(as.z + ad.z) - mx.z);
        sm.w += __expf(leaky(as.w + ad.w) - mx.w);
    }
#pragma unroll
    for (int o = 16; o; o >>= 1) {
        sm.x += __shfl_xor_sync(FULLMASK, sm.x, o);
        sm.y += __shfl_xor_sync(FULLMASK, sm.y, o);
        sm.z += __shfl_xor_sync(FULLMASK, sm.z, o);
        sm.w += __shfl_xor_sync(FULLMASK, sm.w, o);
    }
    float4 inv = make_float4(1.f / (sm.x + 1e-16f), 1.f / (sm.y + 1e-16f),
                             1.f / (sm.z + 1e-16f), 1.f / (sm.w + 1e-16f));
    float mh = sel4(mx, hsel), ih = sel4(inv, hsel), adh = sel4(ad, hsel);

    // phase 3: weighted gather-accumulate, 2 edges per iteration
    acc0 = make_float4(0.f, 0.f, 0.f, 0.f);
    acc1 = make_float4(0.f, 0.f, 0.f, 0.f);
    const int cbase = lane * 8;
    int j = beg;
    for (; j + 2 <= end; j += 2) {
        int s0 = csrc[j], s1 = csrc[j + 1];
        float as0 = asrc[s0 * 4 + hsel];
        float as1 = asrc[s1 * 4 + hsel];
        union { uint4 u; __half2 h2[4]; } u0, u1;
        u0.u = *(const uint4*)(hbuf + (size_t)s0 * HC + cbase);
        u1.u = *(const uint4*)(hbuf + (size_t)s1 * HC + cbase);
        float a0 = __expf(leaky(as0 + adh) - mh) * ih;
        float a1 = __expf(leaky(as1 + adh) - mh) * ih;
        float2 p;
        p = __half22float2(u0.h2[0]); acc0.x = fmaf(p.x, a0, acc0.x); acc0.y = fmaf(p.y, a0, acc0.y);
        p = __half22float2(u0.h2[1]); acc0.z = fmaf(p.x, a0, acc0.z); acc0.w = fmaf(p.y, a0, acc0.w);
        p = __half22float2(u0.h2[2]); acc1.x = fmaf(p.x, a0, acc1.x); acc1.y = fmaf(p.y, a0, acc1.y);
        p = __half22float2(u0.h2[3]); acc1.z = fmaf(p.x, a0, acc1.z); acc1.w = fmaf(p.y, a0, acc1.w);
        p = __half22float2(u1.h2[0]); acc0.x = fmaf(p.x, a1, acc0.x); acc0.y = fmaf(p.y, a1, acc0.y);
        p = __half22float2(u1.h2[1]); acc0.z = fmaf(p.x, a1, acc0.z); acc0.w = fmaf(p.y, a1, acc0.w);
        p = __half22float2(u1.h2[2]); acc1.x = fmaf(p.x, a1, acc1.x); acc1.y = fmaf(p.y, a1, acc1.y);
        p = __half22float2(u1.h2[3]); acc1.z = fmaf(p.x, a1, acc1.z); acc1.w = fmaf(p.y, a1, acc1.w);
    }
    if (j < end) {
        int s = csrc[j];
        float as = asrc[s * 4 + hsel];
        float alpha = __expf(leaky(as + adh) - mh) * ih;
        union { uint4 u; __half2 h2[4]; } uu;
        uu.u = *(const uint4*)(hbuf + (size_t)s * HC + cbase);
        float2 p;
        p = __half22float2(uu.h2[0]); acc0.x = fmaf(p.x, alpha, acc0.x); acc0.y = fmaf(p.y, alpha, acc0.y);
        p = __half22float2(uu.h2[1]); acc0.z = fmaf(p.x, alpha, acc0.z); acc0.w = fmaf(p.y, alpha, acc0.w);
        p = __half22float2(uu.h2[2]); acc1.x = fmaf(p.x, alpha, acc1.x); acc1.y = fmaf(p.y, alpha, acc1.y);
        p = __half22float2(uu.h2[3]); acc1.z = fmaf(p.x, alpha, acc1.z); acc1.w = fmaf(p.y, alpha, acc1.w);
    }
}

// layer 1: concat epilogue (bias + relu) -> act rounded to fp16
__global__ __launch_bounds__(256) void agg1_kernel(const __half* __restrict__ hbuf,
                                                   const float* __restrict__ asrc,
                                                   const float* __restrict__ adst,
                                                   const int* __restrict__ rowptr,
                                                   const int* __restrict__ csrc,
                                                   const float* __restrict__ bias,
                                                   __half* __restrict__ acth, int N) {
    int gw = (blockIdx.x * blockDim.x + threadIdx.x) >> 5;
    int lane = threadIdx.x & 31;
    if (gw >= N) return;
    float4 acc0, acc1;
    agg_core(hbuf, asrc, adst, rowptr, csrc, gw, lane, acc0, acc1);
    int cbase = lane * 8;
    float4 b0 = *(const float4*)(bias + cbase);
    float4 b1 = *(const float4*)(bias + cbase + 4);
    unsigned hh0 = packh2(fmaxf(acc0.x + b0.x, 0.f), fmaxf(acc0.y + b0.y, 0.f));
    unsigned hh1 = packh2(fmaxf(acc0.z + b0.z, 0.f), fmaxf(acc0.w + b0.w, 0.f));
    unsigned hh2 = packh2(fmaxf(acc1.x + b1.x, 0.f), fmaxf(acc1.y + b1.y, 0.f));
    unsigned hh3 = packh2(fmaxf(acc1.z + b1.z, 0.f), fmaxf(acc1.w + b1.w, 0.f));
    *(uint4*)(acth + (size_t)gw * HC + cbase) = make_uint4(hh0, hh1, hh2, hh3);
}

// layer 2: head-mean + bias + relu + softmax(64) -> [N,64]
__global__ __launch_bounds__(256) void agg2_kernel(const __half* __restrict__ hbuf,
                                                   const float* __restrict__ asrc,
                                                   const float* __restrict__ adst,
                                                   const int* __restrict__ rowptr,
                                                   const int* __restrict__ csrc,
                                                   const float* __restrict__ bias,
                                                   float* __restrict__ outp, int N) {
    int gw = (blockIdx.x * blockDim.x + threadIdx.x) >> 5;
    int lane = threadIdx.x & 31;
    if (gw >= N) return;
    float4 acc0, acc1;
    agg_core(hbuf, asrc, adst, rowptr, csrc, gw, lane, acc0, acc1);

    float r[8] = {acc0.x, acc0.y, acc0.z, acc0.w, acc1.x, acc1.y, acc1.z, acc1.w};
#pragma unroll
    for (int k = 0; k < 8; k++) {
        r[k] += __shfl_xor_sync(FULLMASK, r[k], 8);
        r[k] += __shfl_xor_sync(FULLMASK, r[k], 16);
    }
    int cp = (lane & 7) * 8;
    float4 b0 = *(const float4*)(bias + cp);
    float4 b1 = *(const float4*)(bias + cp + 4);
    float bb[8] = {b0.x, b0.y, b0.z, b0.w, b1.x, b1.y, b1.z, b1.w};
    float lm = -1e30f;
#pragma unroll
    for (int k = 0; k < 8; k++) {
        r[k] = fmaxf(0.25f * r[k] + bb[k], 0.f);
        lm = fmaxf(lm, r[k]);
    }
#pragma unroll
    for (int o = 4; o; o >>= 1) lm = fmaxf(lm, __shfl_xor_sync(FULLMASK, lm, o));
    float ls = 0.f;
#pragma unroll
    for (int k = 0; k < 8; k++) { r[k] = __expf(r[k] - lm); ls += r[k]; }
#pragma unroll
    for (int o = 4; o; o >>= 1) ls += __shfl_xor_sync(FULLMASK, ls, o);
    float invs = 1.f / ls;
    if (lane < 8) {
        float* op = outp + (size_t)gw * CH + lane * 8;
        ((float4*)op)[0] = make_float4(r[0] * invs, r[1] * invs, r[2] * invs, r[3] * invs);
        ((float4*)op)[1] = make_float4(r[4] * invs, r[5] * invs, r[6] * invs, r[7] * invs);
    }
}

// ---------------- launch -----------------------------------------------------
extern "C" void kernel_launch(void* const* d_in, const int* in_sizes, int n_in,
                              void* d_out, int out_size) {
    const float* x   = (const float*)d_in[0];
    const int*   ei  = (const int*)d_in[1];
    const float* W1  = (const float*)d_in[2];
    const float* as1 = (const float*)d_in[3];
    const float* ad1 = (const float*)d_in[4];
    const float* b1  = (const float*)d_in[5];
    const float* W2  = (const float*)d_in[6];
    const float* as2 = (const float*)d_in[7];
    const float* ad2 = (const float*)d_in[8];
    const float* b2  = (const float*)d_in[9];
    float* out = (float*)d_out;

    const int N = in_sizes[0] / DIN;
    const int E = in_sizes[1] / 2;

    __half *dH, *dXh, *dAh, *dW1h, *dW2h;
    float *dAs, *dAd;
    int *dRow, *dDeg, *dCur, *dCsr;
    cudaGetSymbolAddress((void**)&dH, g_h);
    cudaGetSymbolAddress((void**)&dXh, g_xh);
    cudaGetSymbolAddress((void**)&dAh, g_acth);
    cudaGetSymbolAddress((void**)&dW1h, g_w1h);
    cudaGetSymbolAddress((void**)&dW2h, g_w2h);
    cudaGetSymbolAddress((void**)&dAs, g_asrc);
    cudaGetSymbolAddress((void**)&dAd, g_adst);
    cudaGetSymbolAddress((void**)&dRow, g_rowptr);
    cudaGetSymbolAddress((void**)&dDeg, g_deg);
    cudaGetSymbolAddress((void**)&dCur, g_cursor);
    cudaGetSymbolAddress((void**)&dCsr, g_csrc);

    cudaFuncSetAttribute(gemm_f16_kernel,
                         cudaFuncAttributeMaxDynamicSharedMemorySize, GEMM_SMEM);

    static cudaStream_t s2 = [] { cudaStream_t s; cudaStreamCreate(&s); return s; }();
    static cudaEvent_t evFork = [] {
        cudaEvent_t e; cudaEventCreateWithFlags(&e, cudaEventDisableTiming); return e; }();
    static cudaEvent_t evJoin = [] {
        cudaEvent_t e; cudaEventCreateWithFlags(&e, cudaEventDisableTiming); return e; }();

    const int warpBlocks = (N * 32 + 255) / 256;
    dim3 gg((N + 127) / 128, HC / 128);

    // fork: CSR build ALONE on s2
    cudaEventRecord(evFork, 0);
    cudaStreamWaitEvent(s2, evFork, 0);

    zero2_kernel<<<(N + 255) / 256, 256, 0, s2>>>(dDeg, dCur, N);
    hist_kernel<<<(E + 255) / 256, 256, 0, s2>>>(ei, E, dDeg);
    scan_kernel<<<1, 1024, 0, s2>>>(dDeg, dRow, N);
    scatter_kernel<<<(E + 255) / 256, 256, 0, s2>>>(ei, E, dRow, dCur, dCsr);
    cudaEventRecord(evJoin, s2);

    // operand prep on main: round x, W1, W2 to fp16
    round_w_kernel<<<(N * DIN / 4 + 255) / 256, 256>>>(x, dXh, N * DIN / 4);
    round_w_kernel<<<(DIN * HC / 4 + 255) / 256, 256>>>(W1, dW1h, DIN * HC / 4);
    round_w_kernel<<<(HC * HC / 4 + 255) / 256, 256>>>(W2, dW2h, HC * HC / 4);

    // layer 1 GEMM (+ fused attention coefficients)
    gemm_f16_kernel<<<gg, 256, GEMM_SMEM>>>(dXh, dW1h, dH, as1, ad1,
                                            dAs, dAd, N, DIN, HC);

    // join: aggregation needs the CSR
    cudaStreamWaitEvent(0, evJoin, 0);
    agg1_kernel<<<warpBlocks, 256>>>(dH, dAs, dAd, dRow, dCsr, b1, dAh, N);

    // layer 2 (serial on main stream; in-place reuse of dH/dAs/dAd is safe)
    gemm_f16_kernel<<<gg, 256, GEMM_SMEM>>>(dAh, dW2h, dH, as2, ad2,
                                            dAs, dAd, N, HC, HC);
    agg2_kernel<<<warpBlocks, 256>>>(dH, dAs, dAd, dRow, dCsr, b2, out, N);
}

// round 17
// speedup vs baseline: 1.3413x; 1.0716x over previous
#include <cuda_runtime.h>
#include <cuda_fp16.h>

#define FULLMASK 0xffffffffu
#define DIN   128
#define HC    256
#define NHEAD 4
#define CH    64
#define NMAX  50016
#define EMAX  900000

// ---------------- scratch (device globals; no allocation allowed) -----------
__device__ __half g_h[(size_t)NMAX * HC];     // GEMM output (fp16, gather-only)
__device__ __half g_xh[(size_t)NMAX * DIN];   // x rounded to fp16
__device__ __half g_acth[(size_t)NMAX * HC];  // act rounded to fp16
__device__ __half g_w1h[DIN * HC];            // W1 rounded to fp16
__device__ __half g_w2h[HC * HC];             // W2 rounded to fp16
__device__ float  g_asrc[NMAX * NHEAD];
__device__ float  g_adst[NMAX * NHEAD];
__device__ int    g_rowptr[NMAX + 1];
__device__ int    g_deg[NMAX];
__device__ int    g_cursor[NMAX];
__device__ int    g_csrc[EMAX];

// ---------------- helpers ---------------------------------------------------
static __device__ __forceinline__ float leaky(float x) { return fmaxf(x, 0.2f * x); }
static __device__ __forceinline__ float sel4(float4 v, int h) {
    return h == 0 ? v.x : (h == 1 ? v.y : (h == 2 ? v.z : v.w));
}
static __device__ __forceinline__ unsigned packh2(float e0, float e1) {
    unsigned r;
    asm("cvt.rn.f16x2.f32 %0, %1, %2;" : "=r"(r) : "f"(e1), "f"(e0));
    return r;
}

static __device__ __forceinline__ void mma16f(float* d, const unsigned* a,
                                              unsigned b0, unsigned b1) {
    asm volatile(
        "mma.sync.aligned.m16n8k16.row.col.f32.f16.f16.f32 "
        "{%0,%1,%2,%3},{%4,%5,%6,%7},{%8,%9},{%0,%1,%2,%3};"
        : "+f"(d[0]), "+f"(d[1]), "+f"(d[2]), "+f"(d[3])
        : "r"(a[0]), "r"(a[1]), "r"(a[2]), "r"(a[3]), "r"(b0), "r"(b1));
}
static __device__ __forceinline__ void ldsm_x4(unsigned& r0, unsigned& r1,
                                               unsigned& r2, unsigned& r3, unsigned a) {
    asm volatile("ldmatrix.sync.aligned.m8n8.x4.shared.b16 {%0,%1,%2,%3}, [%4];"
                 : "=r"(r0), "=r"(r1), "=r"(r2), "=r"(r3) : "r"(a));
}
static __device__ __forceinline__ void ldsm_x2t(unsigned& r0, unsigned& r1, unsigned a) {
    asm volatile("ldmatrix.sync.aligned.m8n8.x2.trans.shared.b16 {%0,%1}, [%2];"
                 : "=r"(r0), "=r"(r1) : "r"(a));
}

// ---------------- operand preparation: round fp32 -> fp16 (single launch) ----
__global__ void prep_kernel(const float* __restrict__ x,
                            const float* __restrict__ w1,
                            const float* __restrict__ w2,
                            __half* __restrict__ xh,
                            __half* __restrict__ w1h,
                            __half* __restrict__ w2h,
                            int qx, int q1, int q2) {
    int i = blockIdx.x * blockDim.x + threadIdx.x;
    const float* src;
    __half* dst;
    int k;
    if (i < qx) {
        src = x; dst = xh; k = i;
    } else if (i < qx + q1) {
        src = w1; dst = w1h; k = i - qx;
    } else if (i < qx + q1 + q2) {
        src = w2; dst = w2h; k = i - qx - q1;
    } else {
        return;
    }
    float4 v = ((const float4*)src)[k];
    ((uint2*)dst)[k] = make_uint2(packh2(v.x, v.y), packh2(v.z, v.w));
}

// ---------------- CSR build --------------------------------------------------
__global__ void zero2_kernel(int* a, int* b, int n) {
    int i = blockIdx.x * blockDim.x + threadIdx.x;
    if (i < n) { a[i] = 0; b[i] = 0; }
}

__global__ void hist_kernel(const int* __restrict__ ei, int E, int* __restrict__ deg) {
    int i = blockIdx.x * blockDim.x + threadIdx.x;
    if (i < E) atomicAdd(&deg[ei[E + i]], 1);
}

__global__ void scan_kernel(const int* __restrict__ deg, int* __restrict__ rowptr, int n) {
    __shared__ int partials[1024];
    int tid = threadIdx.x;
    int per = (n + 1023) >> 10;
    int start = tid * per;
    int end = min(start + per, n);
    int s = 0;
    for (int i = start; i < end; i++) s += deg[i];
    partials[tid] = s;
    __syncthreads();
    for (int d = 1; d < 1024; d <<= 1) {
        int v = (tid >= d) ? partials[tid - d] : 0;
        __syncthreads();
        partials[tid] += v;
        __syncthreads();
    }
    int run = partials[tid] - s;  // exclusive prefix
    for (int i = start; i < end; i++) { rowptr[i] = run; run += deg[i]; }
    if (end == n) rowptr[n] = run;
}

__global__ void scatter_kernel(const int* __restrict__ ei, int E,
                               const int* __restrict__ rowptr,
                               int* __restrict__ cursor, int* __restrict__ csrc) {
    int i = blockIdx.x * blockDim.x + threadIdx.x;
    if (i < E) {
        int d = ei[E + i];
        int pos = atomicAdd(&cursor[d], 1);
        csrc[rowptr[d] + pos] = ei[i];
    }
}

// ---------------- fp16 1-term GEMM + fused attention epilogue ----------------
#define A_ST_H 40
#define B_ST_H 136
#define A_TILE_H (128 * A_ST_H)
#define B_TILE_H (32 * B_ST_H)
#define STAGE_BYTES ((A_TILE_H + B_TILE_H) * 2)
#define GEMM_SMEM (2 * STAGE_BYTES)

__global__ __launch_bounds__(256) void gemm_f16_kernel(
    const __half* __restrict__ AhG,
    const __half* __restrict__ BhG,
    __half* __restrict__ C,
    const float* __restrict__ attS, const float* __restrict__ attD,
    float* __restrict__ asrc, float* __restrict__ adst,
    int M, int K, int Nn) {
    extern __shared__ char smc[];
    const unsigned ubase = (unsigned)__cvta_generic_to_shared(smc);

    const int t = threadIdx.x;
    const int lane = t & 31;
    const int warpid = t >> 5;
    const int wm = warpid & 3;
    const int wn = warpid >> 2;
    const int m0 = blockIdx.x * 128;
    const int n0 = blockIdx.y * 128;
    const int g = lane >> 2, q = lane & 3;

    float acc[2][8][4];
#pragma unroll
    for (int mi = 0; mi < 2; mi++)
#pragma unroll
        for (int ni = 0; ni < 8; ni++)
#pragma unroll
            for (int w = 0; w < 4; w++) acc[mi][ni][w] = 0.f;

    const int ntiles = K >> 5;

    auto issue = [&](int tile, int stage) {
        const int kt = tile << 5;
        unsigned ahB = ubase + stage * STAGE_BYTES;
        unsigned bB  = ahB + A_TILE_H * 2;
#pragma unroll
        for (int i = 0; i < 2; i++) {
            int c = i * 256 + t;
            int row = c >> 2, kq = c & 3;
            bool valid = (m0 + row) < M;
            size_t off = (size_t)(valid ? (m0 + row) : 0) * K + kt + kq * 8;
            unsigned d1 = ahB + row * 80 + kq * 16;
            int sz = valid ? 16 : 0;
            asm volatile("cp.async.ca.shared.global [%0], [%1], 16, %2;"
                         :: "r"(d1), "l"(AhG + off), "r"(sz));
        }
#pragma unroll
        for (int i = 0; i < 2; i++) {
            int c = i * 256 + t;
            int r = c >> 4, c16 = c & 15;
            const __half* src = BhG + (size_t)(kt + r) * Nn + n0 + c16 * 8;
            unsigned dst = bB + r * 272 + c16 * 16;
            asm volatile("cp.async.ca.shared.global [%0], [%1], 16;"
                         :: "r"(dst), "l"(src));
        }
        asm volatile("cp.async.commit_group;");
    };

    issue(0, 0);

    for (int tile = 0; tile < ntiles; tile++) {
        const int cur = tile & 1;
        if (tile + 1 < ntiles) {
            issue(tile + 1, cur ^ 1);
            asm volatile("cp.async.wait_group 1;");
        } else {
            asm volatile("cp.async.wait_group 0;");
        }
        __syncthreads();
        unsigned ahB = ubase + cur * STAGE_BYTES;
        unsigned bB  = ahB + A_TILE_H * 2;

#pragma unroll
        for (int k16 = 0; k16 < 2; k16++) {
            const int kk = k16 * 16;
            unsigned ah[2][4];
#pragma unroll
            for (int mi = 0; mi < 2; mi++) {
                unsigned rowoff = (unsigned)((wm * 32 + mi * 16 + (lane & 15)) * 80 +
                                             (kk + ((lane >> 4) << 3)) * 2);
                ldsm_x4(ah[mi][0], ah[mi][1], ah[mi][2], ah[mi][3], ahB + rowoff);
            }
#pragma unroll
            for (int ni = 0; ni < 8; ni++) {
                unsigned baddr = bB + (unsigned)((kk + (lane & 15)) * 272 +
                                                 (wn * 64 + ni * 8) * 2);
                unsigned b0, b1;
                ldsm_x2t(b0, b1, baddr);
                mma16f(acc[0][ni], ah[0], b0, b1);
                mma16f(acc[1][ni], ah[1], b0, b1);
            }
        }
        __syncthreads();
    }

    // epilogue: store C (fp16) + fused per-head attention dot products
    const int head = blockIdx.y * 2 + wn;
    float2 sS[8], sD[8];
#pragma unroll
    for (int ni = 0; ni < 8; ni++) {
        sS[ni] = *(const float2*)(attS + n0 + wn * 64 + ni * 8 + q * 2);
        sD[ni] = *(const float2*)(attD + n0 + wn * 64 + ni * 8 + q * 2);
    }

#pragma unroll
    for (int mi = 0; mi < 2; mi++) {
        int r0 = m0 + wm * 32 + mi * 16 + g;
        float ps0 = 0.f, pd0 = 0.f, ps1 = 0.f, pd1 = 0.f;
#pragma unroll
        for (int ni = 0; ni < 8; ni++) {
            int cc = n0 + wn * 64 + ni * 8 + q * 2;
            if (r0 < M)
                *(__half2*)(C + (size_t)r0 * Nn + cc) =
                    __floats2half2_rn(acc[mi][ni][0], acc[mi][ni][1]);
            if (r0 + 8 < M)
                *(__half2*)(C + (size_t)(r0 + 8) * Nn + cc) =
                    __floats2half2_rn(acc[mi][ni][2], acc[mi][ni][3]);
            ps0 += acc[mi][ni][0] * sS[ni].x + acc[mi][ni][1] * sS[ni].y;
            pd0 += acc[mi][ni][0] * sD[ni].x + acc[mi][ni][1] * sD[ni].y;
            ps1 += acc[mi][ni][2] * sS[ni].x + acc[mi][ni][3] * sS[ni].y;
            pd1 += acc[mi][ni][2] * sD[ni].x + acc[mi][ni][3] * sD[ni].y;
        }
#pragma unroll
        for (int o = 1; o < 4; o <<= 1) {
            ps0 += __shfl_xor_sync(FULLMASK, ps0, o);
            pd0 += __shfl_xor_sync(FULLMASK, pd0, o);
            ps1 += __shfl_xor_sync(FULLMASK, ps1, o);
            pd1 += __shfl_xor_sync(FULLMASK, pd1, o);
        }
        if (q == 0) {
            if (r0 < M) {
                asrc[r0 * 4 + head] = ps0;
                adst[r0 * 4 + head] = pd0;
            }
            if (r0 + 8 < M) {
                asrc[(r0 + 8) * 4 + head] = ps1;
                adst[(r0 + 8) * 4 + head] = pd1;
            }
        }
    }
}

// ---------------- per-node aggregation core ----------------------------------
// No segment-max pass: e = leaky(a_src+a_dst) is bounded (|e| << 88), so
// exp(e)/sum exp(e) is computed directly. One exp-sum pass + one gather pass.
static __device__ __forceinline__ void agg_core(const __half* __restrict__ hbuf,
                                                const float* __restrict__ asrc,
                                                const float* __restrict__ adst,
                                                const int* __restrict__ rowptr,
                                                const int* __restrict__ csrc,
                                                int gw, int lane,
                                                float4& acc0, float4& acc1) {
    int hsel = lane >> 3;
    int beg = rowptr[gw], end = rowptr[gw + 1];
    float4 ad = *(const float4*)(adst + gw * 4);

    // pass 1: exp-sum (per head)
    float4 sm = make_float4(0.f, 0.f, 0.f, 0.f);
    for (int j = beg + lane; j < end; j += 32) {
        int s = csrc[j];
        float4 as = *(const float4*)(asrc + s * 4);
        sm.x += __expf(leaky(as.x + ad.x));
        sm.y += __expf(leaky(as.y + ad.y));
        sm.z += __expf(leaky(as.z + ad.z));
        sm.w += __expf(leaky(as.w + ad.w));
    }
#pragma unroll
    for (int o = 16; o; o >>= 1) {
        sm.x += __shfl_xor_sync(FULLMASK, sm.x, o);
        sm.y += __shfl_xor_sync(FULLMASK, sm.y, o);
        sm.z += __shfl_xor_sync(FULLMASK, sm.z, o);
        sm.w += __shfl_xor_sync(FULLMASK, sm.w, o);
    }
    float4 inv = make_float4(1.f / (sm.x + 1e-16f), 1.f / (sm.y + 1e-16f),
                             1.f / (sm.z + 1e-16f), 1.f / (sm.w + 1e-16f));
    float ih = sel4(inv, hsel), adh = sel4(ad, hsel);

    // pass 2: weighted gather-accumulate, 2 edges per iteration
    acc0 = make_float4(0.f, 0.f, 0.f, 0.f);
    acc1 = make_float4(0.f, 0.f, 0.f, 0.f);
    const int cbase = lane * 8;
    int j = beg;
    for (; j + 2 <= end; j += 2) {
        int s0 = csrc[j], s1 = csrc[j + 1];
        float as0 = asrc[s0 * 4 + hsel];
        float as1 = asrc[s1 * 4 + hsel];
        union { uint4 u; __half2 h2[4]; } u0, u1;
        u0.u = *(const uint4*)(hbuf + (size_t)s0 * HC + cbase);
        u1.u = *(const uint4*)(hbuf + (size_t)s1 * HC + cbase);
        float a0 = __expf(leaky(as0 + adh)) * ih;
        float a1 = __expf(leaky(as1 + adh)) * ih;
        float2 p;
        p = __half22float2(u0.h2[0]); acc0.x = fmaf(p.x, a0, acc0.x); acc0.y = fmaf(p.y, a0, acc0.y);
        p = __half22float2(u0.h2[1]); acc0.z = fmaf(p.x, a0, acc0.z); acc0.w = fmaf(p.y, a0, acc0.w);
        p = __half22float2(u0.h2[2]); acc1.x = fmaf(p.x, a0, acc1.x); acc1.y = fmaf(p.y, a0, acc1.y);
        p = __half22float2(u0.h2[3]); acc1.z = fmaf(p.x, a0, acc1.z); acc1.w = fmaf(p.y, a0, acc1.w);
        p = __half22float2(u1.h2[0]); acc0.x = fmaf(p.x, a1, acc0.x); acc0.y = fmaf(p.y, a1, acc0.y);
        p = __half22float2(u1.h2[1]); acc0.z = fmaf(p.x, a1, acc0.z); acc0.w = fmaf(p.y, a1, acc0.w);
        p = __half22float2(u1.h2[2]); acc1.x = fmaf(p.x, a1, acc1.x); acc1.y = fmaf(p.y, a1, acc1.y);
        p = __half22float2(u1.h2[3]); acc1.z = fmaf(p.x, a1, acc1.z); acc1.w = fmaf(p.y, a1, acc1.w);
    }
    if (j < end) {
        int s = csrc[j];
        float as = asrc[s * 4 + hsel];
        float alpha = __expf(leaky(as + adh)) * ih;
        union { uint4 u; __half2 h2[4]; } uu;
        uu.u = *(const uint4*)(hbuf + (size_t)s * HC + cbase);
        float2 p;
        p = __half22float2(uu.h2[0]); acc0.x = fmaf(p.x, alpha, acc0.x); acc0.y = fmaf(p.y, alpha, acc0.y);
        p = __half22float2(uu.h2[1]); acc0.z = fmaf(p.x, alpha, acc0.z); acc0.w = fmaf(p.y, alpha, acc0.w);
        p = __half22float2(uu.h2[2]); acc1.x = fmaf(p.x, alpha, acc1.x); acc1.y = fmaf(p.y, alpha, acc1.y);
        p = __half22float2(uu.h2[3]); acc1.z = fmaf(p.x, alpha, acc1.z); acc1.w = fmaf(p.y, alpha, acc1.w);
    }
}

// layer 1: concat epilogue (bias + relu) -> act rounded to fp16
__global__ __launch_bounds__(256) void agg1_kernel(const __half* __restrict__ hbuf,
                                                   const float* __restrict__ asrc,
                                                   const float* __restrict__ adst,
                                                   const int* __restrict__ rowptr,
                                                   const int* __restrict__ csrc,
                                                   const float* __restrict__ bias,
                                                   __half* __restrict__ acth, int N) {
    int gw = (blockIdx.x * blockDim.x + threadIdx.x) >> 5;
    int lane = threadIdx.x & 31;
    if (gw >= N) return;
    float4 acc0, acc1;
    agg_core(hbuf, asrc, adst, rowptr, csrc, gw, lane, acc0, acc1);
    int cbase = lane * 8;
    float4 b0 = *(const float4*)(bias + cbase);
    float4 b1 = *(const float4*)(bias + cbase + 4);
    unsigned hh0 = packh2(fmaxf(acc0.x + b0.x, 0.f), fmaxf(acc0.y + b0.y, 0.f));
    unsigned hh1 = packh2(fmaxf(acc0.z + b0.z, 0.f), fmaxf(acc0.w + b0.w, 0.f));
    unsigned hh2 = packh2(fmaxf(acc1.x + b1.x, 0.f), fmaxf(acc1.y + b1.y, 0.f));
    unsigned hh3 = packh2(fmaxf(acc1.z + b1.z, 0.f), fmaxf(acc1.w + b1.w, 0.f));
    *(uint4*)(acth + (size_t)gw * HC + cbase) = make_uint4(hh0, hh1, hh2, hh3);
}

// layer 2: head-mean + bias + relu + softmax(64) -> [N,64]
__global__ __launch_bounds__(256) void agg2_kernel(const __half* __restrict__ hbuf,
                                                   const float* __restrict__ asrc,
                                                   const float* __restrict__ adst,
                                                   const int* __restrict__ rowptr,
                                                   const int* __restrict__ csrc,
                                                   const float* __restrict__ bias,
                                                   float* __restrict__ outp, int N) {
    int gw = (blockIdx.x * blockDim.x + threadIdx.x) >> 5;
    int lane = threadIdx.x & 31;
    if (gw >= N) return;
    float4 acc0, acc1;
    agg_core(hbuf, asrc, adst, rowptr, csrc, gw, lane, acc0, acc1);

    float r[8] = {acc0.x, acc0.y, acc0.z, acc0.w, acc1.x, acc1.y, acc1.z, acc1.w};
#pragma unroll
    for (int k = 0; k < 8; k++) {
        r[k] += __shfl_xor_sync(FULLMASK, r[k], 8);
        r[k] += __shfl_xor_sync(FULLMASK, r[k], 16);
    }
    int cp = (lane & 7) * 8;
    float4 b0 = *(const float4*)(bias + cp);
    float4 b1 = *(const float4*)(bias + cp + 4);
    float bb[8] = {b0.x, b0.y, b0.z, b0.w, b1.x, b1.y, b1.z, b1.w};
    float lm = -1e30f;
#pragma unroll
    for (int k = 0; k < 8; k++) {
        r[k] = fmaxf(0.25f * r[k] + bb[k], 0.f);
        lm = fmaxf(lm, r[k]);
    }
#pragma unroll
    for (int o = 4; o; o >>= 1) lm = fmaxf(lm, __shfl_xor_sync(FULLMASK, lm, o));
    float ls = 0.f;
#pragma unroll
    for (int k = 0; k < 8; k++) { r[k] = __expf(r[k] - lm); ls += r[k]; }
#pragma unroll
    for (int o = 4; o; o >>= 1) ls += __shfl_xor_sync(FULLMASK, ls, o);
    float invs = 1.f / ls;
    if (lane < 8) {
        float* op = outp + (size_t)gw * CH + lane * 8;
        ((float4*)op)[0] = make_float4(r[0] * invs, r[1] * invs, r[2] * invs, r[3] * invs);
        ((float4*)op)[1] = make_float4(r[4] * invs, r[5] * invs, r[6] * invs, r[7] * invs);
    }
}

// ---------------- launch -----------------------------------------------------
extern "C" void kernel_launch(void* const* d_in, const int* in_sizes, int n_in,
                              void* d_out, int out_size) {
    const float* x   = (const float*)d_in[0];
    const int*   ei  = (const int*)d_in[1];
    const float* W1  = (const float*)d_in[2];
    const float* as1 = (const float*)d_in[3];
    const float* ad1 = (const float*)d_in[4];
    const float* b1  = (const float*)d_in[5];
    const float* W2  = (const float*)d_in[6];
    const float* as2 = (const float*)d_in[7];
    const float* ad2 = (const float*)d_in[8];
    const float* b2  = (const float*)d_in[9];
    float* out = (float*)d_out;

    const int N = in_sizes[0] / DIN;
    const int E = in_sizes[1] / 2;

    __half *dH, *dXh, *dAh, *dW1h, *dW2h;
    float *dAs, *dAd;
    int *dRow, *dDeg, *dCur, *dCsr;
    cudaGetSymbolAddress((void**)&dH, g_h);
    cudaGetSymbolAddress((void**)&dXh, g_xh);
    cudaGetSymbolAddress((void**)&dAh, g_acth);
    cudaGetSymbolAddress((void**)&dW1h, g_w1h);
    cudaGetSymbolAddress((void**)&dW2h, g_w2h);
    cudaGetSymbolAddress((void**)&dAs, g_asrc);
    cudaGetSymbolAddress((void**)&dAd, g_adst);
    cudaGetSymbolAddress((void**)&dRow, g_rowptr);
    cudaGetSymbolAddress((void**)&dDeg, g_deg);
    cudaGetSymbolAddress((void**)&dCur, g_cursor);
    cudaGetSymbolAddress((void**)&dCsr, g_csrc);

    cudaFuncSetAttribute(gemm_f16_kernel,
                         cudaFuncAttributeMaxDynamicSharedMemorySize, GEMM_SMEM);

    static cudaStream_t s2 = [] { cudaStream_t s; cudaStreamCreate(&s); return s; }();
    static cudaEvent_t evFork = [] {
        cudaEvent_t e; cudaEventCreateWithFlags(&e, cudaEventDisableTiming); return e; }();
    static cudaEvent_t evJoin = [] {
        cudaEvent_t e; cudaEventCreateWithFlags(&e, cudaEventDisableTiming); return e; }();

    const int warpBlocks = (N * 32 + 255) / 256;
    dim3 gg((N + 127) / 128, HC / 128);

    // fork: CSR build ALONE on s2
    cudaEventRecord(evFork, 0);
    cudaStreamWaitEvent(s2, evFork, 0);

    zero2_kernel<<<(N + 255) / 256, 256, 0, s2>>>(dDeg, dCur, N);
    hist_kernel<<<(E + 255) / 256, 256, 0, s2>>>(ei, E, dDeg);
    scan_kernel<<<1, 1024, 0, s2>>>(dDeg, dRow, N);
    scatter_kernel<<<(E + 255) / 256, 256, 0, s2>>>(ei, E, dRow, dCur, dCsr);
    cudaEventRecord(evJoin, s2);

    // operand prep on main: round x, W1, W2 to fp16 in ONE launch
    const int qx = N * DIN / 4;
    const int q1 = DIN * HC / 4;
    const int q2 = HC * HC / 4;
    prep_kernel<<<(qx + q1 + q2 + 255) / 256, 256>>>(x, W1, W2, dXh, dW1h, dW2h,
                                                     qx, q1, q2);

    // layer 1 GEMM (+ fused attention coefficients)
    gemm_f16_kernel<<<gg, 256, GEMM_SMEM>>>(dXh, dW1h, dH, as1, ad1,
                                            dAs, dAd, N, DIN, HC);

    // join: aggregation needs the CSR
    cudaStreamWaitEvent(0, evJoin, 0);
    agg1_kernel<<<warpBlocks, 256>>>(dH, dAs, dAd, dRow, dCsr, b1, dAh, N);

    // layer 2 (serial on main stream; in-place reuse of dH/dAs/dAd is safe)
    gemm_f16_kernel<<<gg, 256, GEMM_SMEM>>>(dAh, dW2h, dH, as2, ad2,
                                            dAs, dAd, N, HC, HC);
    agg2_kernel<<<warpBlocks, 256>>>(dH, dAs, dAd, dRow, dCsr, b2, out, N);
}